// round 1
// baseline (speedup 1.0000x reference)
#include <cuda_runtime.h>
#include <math.h>

#define B_      4
#define L_      4096
#define DIM_    1024
#define STATE_  16
#define NC_     64              // chunks per batch
#define CHUNK_  (L_ / NC_)      // 64
#define WARM_   256             // warm-up steps (contraction ~0.95/step -> ~3e-6 residual)

// ---------------- scratch (no allocations allowed) ----------------
__device__ float g_scale;                       // spectral-norm scale for A
__device__ float g_dt[B_ * L_];                 // dt[b][t]
__device__ float g_bx[B_ * L_ * STATE_];        // Bx[b][t][i]
__device__ float g_states[B_ * L_ * STATE_];    // normalized states s[b][t][i]

// =================================================================
// K0: spectral scale. Exact fast path: sigma_max <= ||A||_F, so if
// ||A||_F <= 0.99 then scale == 1 exactly. Fallback: power iteration.
// =================================================================
__global__ void k0_scale(const float* __restrict__ A) {
    __shared__ float sA[256];
    __shared__ float red[256];
    int t = threadIdx.x;
    float a = A[t];
    sA[t] = a;
    red[t] = a * a;
    __syncthreads();
    for (int s = 128; s > 0; s >>= 1) {
        if (t < s) red[t] += red[t + s];
        __syncthreads();
    }
    if (t == 0) {
        float scale = 1.0f;
        if (red[0] > 0.9801f) {   // Frobenius bound fails -> actually compute sigma_max
            float v[16];
            #pragma unroll
            for (int k = 0; k < 16; k++) v[k] = 1.0f;
            for (int it = 0; it < 400; ++it) {
                float u[16];
                for (int r = 0; r < 16; r++) {
                    float acc = 0.f;
                    for (int c = 0; c < 16; c++) acc = fmaf(sA[r * 16 + c], v[c], acc);
                    u[r] = acc;
                }
                float w2[16]; float nn = 0.f;
                for (int c = 0; c < 16; c++) {
                    float acc = 0.f;
                    for (int r = 0; r < 16; r++) acc = fmaf(sA[r * 16 + c], u[r], acc);
                    w2[c] = acc; nn += acc * acc;
                }
                float inv = rsqrtf(fmaxf(nn, 1e-30f));
                for (int c = 0; c < 16; c++) v[c] = w2[c] * inv;
            }
            float sig2 = 0.f;
            for (int r = 0; r < 16; r++) {
                float acc = 0.f;
                for (int c = 0; c < 16; c++) acc = fmaf(sA[r * 16 + c], v[c], acc);
                sig2 += acc * acc;
            }
            float sigma = sqrtf(sig2);
            if (sigma > 0.99f) scale = 0.99f / sigma;
        }
        g_scale = scale;
    }
}

// =================================================================
// K1: per-row projections. One warp per (b,t) row of x.
//   Bx[i] = sum_d x[d]*W_B[i][d]   (i = 0..15)
//   dt    = clip(softplus(sum_d x[d]*dt_w[d] + dt_b), 1e-3, 0.1)
// Lane partials over d-slices, 5-level butterfly reduction.
// =================================================================
__global__ void __launch_bounds__(256) k1_proj(const float* __restrict__ x,
                                               const float* __restrict__ W_B,
                                               const float* __restrict__ dt_w,
                                               const float* __restrict__ dt_b) {
    int warp = (blockIdx.x * blockDim.x + threadIdx.x) >> 5;   // row index b*L + t
    int lane = threadIdx.x & 31;
    if (warp >= B_ * L_) return;

    const float4* xr = reinterpret_cast<const float4*>(x + (size_t)warp * DIM_) + lane;
    float4 xv[8];
    #pragma unroll
    for (int k = 0; k < 8; k++) xv[k] = xr[k * 32];

    float acc[17];
    #pragma unroll
    for (int i = 0; i < 16; i++) {
        const float4* wr = reinterpret_cast<const float4*>(W_B + (size_t)i * DIM_) + lane;
        float a0 = 0.f, a1 = 0.f, a2 = 0.f, a3 = 0.f;
        #pragma unroll
        for (int k = 0; k < 8; k++) {
            float4 w4 = wr[k * 32];
            a0 = fmaf(xv[k].x, w4.x, a0);
            a1 = fmaf(xv[k].y, w4.y, a1);
            a2 = fmaf(xv[k].z, w4.z, a2);
            a3 = fmaf(xv[k].w, w4.w, a3);
        }
        acc[i] = (a0 + a1) + (a2 + a3);
    }
    {
        const float4* wr = reinterpret_cast<const float4*>(dt_w) + lane;
        float a0 = 0.f, a1 = 0.f, a2 = 0.f, a3 = 0.f;
        #pragma unroll
        for (int k = 0; k < 8; k++) {
            float4 w4 = wr[k * 32];
            a0 = fmaf(xv[k].x, w4.x, a0);
            a1 = fmaf(xv[k].y, w4.y, a1);
            a2 = fmaf(xv[k].z, w4.z, a2);
            a3 = fmaf(xv[k].w, w4.w, a3);
        }
        acc[16] = (a0 + a1) + (a2 + a3);
    }

    #pragma unroll
    for (int m = 16; m >= 1; m >>= 1) {
        #pragma unroll
        for (int i = 0; i < 17; i++)
            acc[i] += __shfl_xor_sync(0xffffffffu, acc[i], m);
    }

    if (lane == 0) {
        float4* bo = reinterpret_cast<float4*>(g_bx + (size_t)warp * STATE_);
        bo[0] = make_float4(acc[0],  acc[1],  acc[2],  acc[3]);
        bo[1] = make_float4(acc[4],  acc[5],  acc[6],  acc[7]);
        bo[2] = make_float4(acc[8],  acc[9],  acc[10], acc[11]);
        bo[3] = make_float4(acc[12], acc[13], acc[14], acc[15]);
        float z  = acc[16] + dt_b[0];
        float sp = (z > 15.f) ? z : log1pf(expf(z));
        g_dt[warp] = fminf(fmaxf(sp, 0.001f), 0.1f);
    }
}

// =================================================================
// K2: chunked sequential scan with warm-up.
// One 16-lane group per (batch, chunk); 2 groups per warp (same chunk,
// different batch -> zero divergence). Lane i owns state component i.
// Per step: fused sum/sumsq butterfly runs concurrently with the
// next-step matvec A'h (ln_w folded into A columns), so the critical
// path is max(butterfly, matvec) + rsqrt + combine.
// =================================================================
__global__ void __launch_bounds__(32) k2_scan(const float* __restrict__ A,
                                              const float* __restrict__ state_in,
                                              const float* __restrict__ ln_w,
                                              const float* __restrict__ ln_b) {
    const unsigned FULL = 0xffffffffu;
    int lane = threadIdx.x;           // 0..31
    int seg  = lane >> 4;             // group within warp
    int i    = lane & 15;             // state component
    int gidx = blockIdx.x * 2 + seg;  // 0..255
    int b     = gidx & 3;             // batch   (differs across segs)
    int chunk = gidx >> 2;            // chunk   (same across segs -> convergent)
    int cs   = chunk * CHUNK_;
    int ws   = cs - WARM_; if (ws < 0) ws = 0;
    int tend = cs + CHUNK_;

    float scale = g_scale;

    // ln vectors (compile-time indexed only)
    float w_[16], b_[16];
    #pragma unroll
    for (int j = 0; j < 16; j += 4) {
        float4 t4 = *reinterpret_cast<const float4*>(ln_w + j);
        w_[j] = t4.x; w_[j + 1] = t4.y; w_[j + 2] = t4.z; w_[j + 3] = t4.w;
        float4 u4 = *reinterpret_cast<const float4*>(ln_b + j);
        b_[j] = u4.x; b_[j + 1] = u4.y; b_[j + 2] = u4.z; b_[j + 3] = u4.w;
    }
    // row i of An = scale*A, and A' = An * diag(ln_w)
    float an[16], ap[16];
    #pragma unroll
    for (int j = 0; j < 16; j += 4) {
        float4 a4 = *reinterpret_cast<const float4*>(A + i * 16 + j);
        an[j] = a4.x * scale; an[j + 1] = a4.y * scale;
        an[j + 2] = a4.z * scale; an[j + 3] = a4.w * scale;
    }
    float aw1 = 0.f, ab = 0.f;
    #pragma unroll
    for (int j = 0; j < 16; j++) {
        ap[j] = an[j] * w_[j];
        aw1  += ap[j];
        ab    = fmaf(an[j], b_[j], ab);
    }
    float wi = ln_w[i];
    float bi = ln_b[i];

    const float* dtp = g_dt + (size_t)b * L_;
    const float* bxp = g_bx + (size_t)b * L_ * STATE_ + i;
    float*       stp = g_states + (size_t)b * L_ * STATE_ + i;

    // prologue: h_ws = s0 + dt[ws]*(An s0) + bx[ws]
    float s0 = (ws == 0) ? state_in[b * STATE_ + i] : 0.f;
    float p0 = 0.f, p1 = 0.f, p2 = 0.f, p3 = 0.f;
    #pragma unroll
    for (int j = 0; j < 16; j += 4) {
        p0 = fmaf(an[j],     __shfl_sync(FULL, s0, j,     16), p0);
        p1 = fmaf(an[j + 1], __shfl_sync(FULL, s0, j + 1, 16), p1);
        p2 = fmaf(an[j + 2], __shfl_sync(FULL, s0, j + 2, 16), p2);
        p3 = fmaf(an[j + 3], __shfl_sync(FULL, s0, j + 3, 16), p3);
    }
    float g0 = (p0 + p1) + (p2 + p3);
    float h = fmaf(dtp[ws], g0, s0) + bxp[(size_t)ws * STATE_];

    // prefetch queue, depth 2 (clamped indices stay in-bounds)
    int tp1 = ws + 1; if (tp1 > L_ - 1) tp1 = L_ - 1;
    int tp2 = ws + 2; if (tp2 > L_ - 1) tp2 = L_ - 1;
    float dtA = dtp[tp1], bxA = bxp[(size_t)tp1 * STATE_];
    float dtB = dtp[tp2], bxB = bxp[(size_t)tp2 * STATE_];

    for (int t = ws; t < tend; ++t) {
        // fused mean / mean-of-squares butterfly over the 16-lane group
        float u = h, q = h * h;
        #pragma unroll
        for (int m = 8; m >= 1; m >>= 1) {
            u += __shfl_xor_sync(FULL, u, m);
            q += __shfl_xor_sync(FULL, q, m);
        }
        // concurrent matvec g = A' h (depends only on h)
        float m0 = 0.f, m1 = 0.f, m2 = 0.f, m3 = 0.f;
        #pragma unroll
        for (int j = 0; j < 16; j += 4) {
            m0 = fmaf(ap[j],     __shfl_sync(FULL, h, j,     16), m0);
            m1 = fmaf(ap[j + 1], __shfl_sync(FULL, h, j + 1, 16), m1);
            m2 = fmaf(ap[j + 2], __shfl_sync(FULL, h, j + 2, 16), m2);
            m3 = fmaf(ap[j + 3], __shfl_sync(FULL, h, j + 3, 16), m3);
        }
        float g = (m0 + m1) + (m2 + m3);

        float mu    = u * 0.0625f;
        float var   = fmaf(-mu, mu, q * 0.0625f);
        float alpha = rsqrtf(var + 1e-5f);
        float hm    = h - mu;

        if (t >= cs) stp[(size_t)t * STATE_] = fmaf(alpha * hm, wi, bi);

        // next pre-norm: h' = alpha*[(h-mu)*w + dt'*(g - mu*aw1)] + b + dt'*ab + bx'
        float dtn = dtA, bxn = bxA;
        dtA = dtB; bxA = bxB;
        int tn = t + 3; if (tn > L_ - 1) tn = L_ - 1;
        dtB = dtp[tn]; bxB = bxp[(size_t)tn * STATE_];

        float t1 = fmaf(-mu, aw1, g);
        float t2 = fmaf(dtn, t1, hm * wi);
        h = fmaf(alpha, t2, fmaf(dtn, ab, bi) + bxn);
    }
}

// =================================================================
// K3: y[b][t][d] = sum_i states[b][t][i]*W_C[d][i] + D[d]*x[b][t][d]
// Block = 4 rows, thread = 4 consecutive d. W_C[d..d+3][:] cached in
// registers and reused across the 4 rows. Also writes new_state tail.
// =================================================================
__device__ __forceinline__ float dot16_(const float4* w,
                                        float4 s0, float4 s1, float4 s2, float4 s3) {
    float a0 = w[0].x * s0.x; a0 = fmaf(w[0].y, s0.y, a0);
    a0 = fmaf(w[0].z, s0.z, a0); a0 = fmaf(w[0].w, s0.w, a0);
    float a1 = w[1].x * s1.x; a1 = fmaf(w[1].y, s1.y, a1);
    a1 = fmaf(w[1].z, s1.z, a1); a1 = fmaf(w[1].w, s1.w, a1);
    float a2 = w[2].x * s2.x; a2 = fmaf(w[2].y, s2.y, a2);
    a2 = fmaf(w[2].z, s2.z, a2); a2 = fmaf(w[2].w, s2.w, a2);
    float a3 = w[3].x * s3.x; a3 = fmaf(w[3].y, s3.y, a3);
    a3 = fmaf(w[3].z, s3.z, a3); a3 = fmaf(w[3].w, s3.w, a3);
    return (a0 + a1) + (a2 + a3);
}

__global__ void __launch_bounds__(256) k3_out(const float* __restrict__ x,
                                              const float* __restrict__ W_C,
                                              const float* __restrict__ D,
                                              float* __restrict__ out,
                                              int write_tail) {
    int rb = blockIdx.x * 4;
    int d  = threadIdx.x * 4;

    float4 wc[16];   // W_C[d+r][0..15] for r=0..3
    const float4* wp = reinterpret_cast<const float4*>(W_C + (size_t)d * STATE_);
    #pragma unroll
    for (int k = 0; k < 16; k++) wc[k] = wp[k];
    float4 dd = *reinterpret_cast<const float4*>(D + d);

    #pragma unroll
    for (int r = 0; r < 4; r++) {
        int row = rb + r;
        const float* st = g_states + (size_t)row * STATE_;
        float4 s0 = *reinterpret_cast<const float4*>(st);
        float4 s1 = *reinterpret_cast<const float4*>(st + 4);
        float4 s2 = *reinterpret_cast<const float4*>(st + 8);
        float4 s3 = *reinterpret_cast<const float4*>(st + 12);
        float4 xd = *reinterpret_cast<const float4*>(x + (size_t)row * DIM_ + d);

        float4 y;
        y.x = dot16_(wc + 0,  s0, s1, s2, s3);
        y.y = dot16_(wc + 4,  s0, s1, s2, s3);
        y.z = dot16_(wc + 8,  s0, s1, s2, s3);
        y.w = dot16_(wc + 12, s0, s1, s2, s3);
        y.x = fmaf(dd.x, xd.x, y.x);
        y.y = fmaf(dd.y, xd.y, y.y);
        y.z = fmaf(dd.z, xd.z, y.z);
        y.w = fmaf(dd.w, xd.w, y.w);
        *reinterpret_cast<float4*>(out + (size_t)row * DIM_ + d) = y;
    }

    // new_state = states[:, L-1, :]
    if (write_tail && blockIdx.x == 0 && threadIdx.x < B_ * STATE_) {
        int bb = threadIdx.x >> 4, ii = threadIdx.x & 15;
        out[(size_t)B_ * L_ * DIM_ + threadIdx.x] =
            g_states[((size_t)bb * L_ + (L_ - 1)) * STATE_ + ii];
    }
}

// =================================================================
extern "C" void kernel_launch(void* const* d_in, const int* in_sizes, int n_in,
                              void* d_out, int out_size) {
    const float* x     = (const float*)d_in[0];
    const float* state = (const float*)d_in[1];
    const float* A     = (const float*)d_in[2];
    const float* W_B   = (const float*)d_in[3];
    const float* W_C   = (const float*)d_in[4];
    const float* D     = (const float*)d_in[5];
    const float* dt_w  = (const float*)d_in[6];
    const float* dt_b  = (const float*)d_in[7];
    const float* ln_w  = (const float*)d_in[8];
    const float* ln_b  = (const float*)d_in[9];
    float* out = (float*)d_out;

    k0_scale<<<1, 256>>>(A);
    k1_proj<<<(B_ * L_ * 32) / 256, 256>>>(x, W_B, dt_w, dt_b);          // 2048 blocks
    k2_scan<<<(B_ * NC_) / 2, 32>>>(A, state, ln_w, ln_b);               // 128 blocks
    int tail = (out_size >= B_ * L_ * DIM_ + B_ * STATE_) ? 1 : 0;
    k3_out<<<(B_ * L_) / 4, 256>>>(x, W_C, D, out, tail);                // 4096 blocks
}

// round 2
// speedup vs baseline: 1.5182x; 1.5182x over previous
#include <cuda_runtime.h>
#include <math.h>

#define B_      4
#define L_      4096
#define DIM_    1024
#define STATE_  16
#define NC_     64              // chunks per batch
#define CHUNK_  (L_ / NC_)      // 64
#define WARM_   128             // contraction ~0.945/step -> ~7e-4 state residual -> ~3e-5 in y

// ---------------- scratch (no allocations allowed) ----------------
__device__ float g_scale;                       // spectral-norm scale for A
__device__ float g_dt[B_ * L_];                 // dt[b][t]
__device__ float g_bx[B_ * L_ * STATE_];        // Bx[b][t][i]
__device__ float g_states[B_ * L_ * STATE_];    // normalized states s[b][t][i]

// =================================================================
// K0: spectral scale. Exact fast path: sigma_max <= ||A||_F, so if
// ||A||_F <= 0.99 then scale == 1 exactly. Fallback: power iteration.
// =================================================================
__global__ void k0_scale(const float* __restrict__ A) {
    __shared__ float sA[256];
    __shared__ float red[256];
    int t = threadIdx.x;
    float a = A[t];
    sA[t] = a;
    red[t] = a * a;
    __syncthreads();
    for (int s = 128; s > 0; s >>= 1) {
        if (t < s) red[t] += red[t + s];
        __syncthreads();
    }
    if (t == 0) {
        float scale = 1.0f;
        if (red[0] > 0.9801f) {   // Frobenius bound fails -> actually compute sigma_max
            float v[16];
            #pragma unroll
            for (int k = 0; k < 16; k++) v[k] = 1.0f;
            for (int it = 0; it < 400; ++it) {
                float u[16];
                for (int r = 0; r < 16; r++) {
                    float acc = 0.f;
                    for (int c = 0; c < 16; c++) acc = fmaf(sA[r * 16 + c], v[c], acc);
                    u[r] = acc;
                }
                float w2[16]; float nn = 0.f;
                for (int c = 0; c < 16; c++) {
                    float acc = 0.f;
                    for (int r = 0; r < 16; r++) acc = fmaf(sA[r * 16 + c], u[r], acc);
                    w2[c] = acc; nn += acc * acc;
                }
                float inv = rsqrtf(fmaxf(nn, 1e-30f));
                for (int c = 0; c < 16; c++) v[c] = w2[c] * inv;
            }
            float sig2 = 0.f;
            for (int r = 0; r < 16; r++) {
                float acc = 0.f;
                for (int c = 0; c < 16; c++) acc = fmaf(sA[r * 16 + c], v[c], acc);
                sig2 += acc * acc;
            }
            float sigma = sqrtf(sig2);
            if (sigma > 0.99f) scale = 0.99f / sigma;
        }
        g_scale = scale;
    }
}

// =================================================================
// K1: per-row projections, TWO rows per warp (W_B stream shared).
//   Bx[i] = sum_d x[d]*W_B[i][d]   (i = 0..15)
//   dt    = clip(softplus(sum_d x[d]*dt_w[d] + dt_b), 1e-3, 0.1)
// =================================================================
__global__ void __launch_bounds__(256) k1_proj(const float* __restrict__ x,
                                               const float* __restrict__ W_B,
                                               const float* __restrict__ dt_w,
                                               const float* __restrict__ dt_b) {
    int warp = (blockIdx.x * blockDim.x + threadIdx.x) >> 5;   // warp id
    int lane = threadIdx.x & 31;
    int r0 = warp * 2;                // rows r0, r0+1
    if (r0 >= B_ * L_) return;

    const float4* xr0 = reinterpret_cast<const float4*>(x + (size_t)r0 * DIM_) + lane;
    const float4* xr1 = reinterpret_cast<const float4*>(x + (size_t)(r0 + 1) * DIM_) + lane;
    float4 xv0[8], xv1[8];
    #pragma unroll
    for (int k = 0; k < 8; k++) { xv0[k] = xr0[k * 32]; xv1[k] = xr1[k * 32]; }

    float acc0[17], acc1[17];
    #pragma unroll
    for (int i = 0; i < 17; i++) {
        const float* wrow = (i < 16) ? (W_B + (size_t)i * DIM_) : dt_w;
        const float4* wr = reinterpret_cast<const float4*>(wrow) + lane;
        float a0 = 0.f, a1 = 0.f, a2 = 0.f, a3 = 0.f;
        float b0 = 0.f, b1 = 0.f, b2 = 0.f, b3 = 0.f;
        #pragma unroll
        for (int k = 0; k < 8; k++) {
            float4 w4 = wr[k * 32];
            a0 = fmaf(xv0[k].x, w4.x, a0);
            a1 = fmaf(xv0[k].y, w4.y, a1);
            a2 = fmaf(xv0[k].z, w4.z, a2);
            a3 = fmaf(xv0[k].w, w4.w, a3);
            b0 = fmaf(xv1[k].x, w4.x, b0);
            b1 = fmaf(xv1[k].y, w4.y, b1);
            b2 = fmaf(xv1[k].z, w4.z, b2);
            b3 = fmaf(xv1[k].w, w4.w, b3);
        }
        acc0[i] = (a0 + a1) + (a2 + a3);
        acc1[i] = (b0 + b1) + (b2 + b3);
    }

    #pragma unroll
    for (int m = 16; m >= 1; m >>= 1) {
        #pragma unroll
        for (int i = 0; i < 17; i++) {
            acc0[i] += __shfl_xor_sync(0xffffffffu, acc0[i], m);
            acc1[i] += __shfl_xor_sync(0xffffffffu, acc1[i], m);
        }
    }

    if (lane == 0) {
        float dtb = dt_b[0];
        float4* bo0 = reinterpret_cast<float4*>(g_bx + (size_t)r0 * STATE_);
        bo0[0] = make_float4(acc0[0],  acc0[1],  acc0[2],  acc0[3]);
        bo0[1] = make_float4(acc0[4],  acc0[5],  acc0[6],  acc0[7]);
        bo0[2] = make_float4(acc0[8],  acc0[9],  acc0[10], acc0[11]);
        bo0[3] = make_float4(acc0[12], acc0[13], acc0[14], acc0[15]);
        float z0  = acc0[16] + dtb;
        float sp0 = (z0 > 15.f) ? z0 : log1pf(expf(z0));
        g_dt[r0] = fminf(fmaxf(sp0, 0.001f), 0.1f);

        float4* bo1 = reinterpret_cast<float4*>(g_bx + (size_t)(r0 + 1) * STATE_);
        bo1[0] = make_float4(acc1[0],  acc1[1],  acc1[2],  acc1[3]);
        bo1[1] = make_float4(acc1[4],  acc1[5],  acc1[6],  acc1[7]);
        bo1[2] = make_float4(acc1[8],  acc1[9],  acc1[10], acc1[11]);
        bo1[3] = make_float4(acc1[12], acc1[13], acc1[14], acc1[15]);
        float z1  = acc1[16] + dtb;
        float sp1 = (z1 > 15.f) ? z1 : log1pf(expf(z1));
        g_dt[r0 + 1] = fminf(fmaxf(sp1, 0.001f), 0.1f);
    }
}

// =================================================================
// K2: chunked sequential scan with warm-up.
// One 16-lane group per (batch, chunk); 2 groups per warp.
// The matvec's shfl(h, j) gives EVERY lane all 16 h_j values, so
// mean and mean-of-squares come from the same shfl results — no
// separate butterfly reduction. Step critical path ~ shfl + fma tree.
// =================================================================
__global__ void __launch_bounds__(32) k2_scan(const float* __restrict__ A,
                                              const float* __restrict__ state_in,
                                              const float* __restrict__ ln_w,
                                              const float* __restrict__ ln_b) {
    const unsigned FULL = 0xffffffffu;
    int lane = threadIdx.x;           // 0..31
    int seg  = lane >> 4;             // group within warp
    int i    = lane & 15;             // state component
    int gidx = blockIdx.x * 2 + seg;  // 0..255
    int b     = gidx & 3;             // batch   (differs across segs)
    int chunk = gidx >> 2;            // chunk   (same across segs -> convergent)
    int cs   = chunk * CHUNK_;
    int ws   = cs - WARM_; if (ws < 0) ws = 0;
    int tend = cs + CHUNK_;

    float scale = g_scale;

    float w_[16], b_[16];
    #pragma unroll
    for (int j = 0; j < 16; j += 4) {
        float4 t4 = *reinterpret_cast<const float4*>(ln_w + j);
        w_[j] = t4.x; w_[j + 1] = t4.y; w_[j + 2] = t4.z; w_[j + 3] = t4.w;
        float4 u4 = *reinterpret_cast<const float4*>(ln_b + j);
        b_[j] = u4.x; b_[j + 1] = u4.y; b_[j + 2] = u4.z; b_[j + 3] = u4.w;
    }
    // row i of An = scale*A, and A' = An * diag(ln_w)
    float an[16], ap[16];
    #pragma unroll
    for (int j = 0; j < 16; j += 4) {
        float4 a4 = *reinterpret_cast<const float4*>(A + i * 16 + j);
        an[j] = a4.x * scale; an[j + 1] = a4.y * scale;
        an[j + 2] = a4.z * scale; an[j + 3] = a4.w * scale;
    }
    float aw1 = 0.f, ab = 0.f;
    #pragma unroll
    for (int j = 0; j < 16; j++) {
        ap[j] = an[j] * w_[j];
        aw1  += ap[j];
        ab    = fmaf(an[j], b_[j], ab);
    }
    float wi = w_[0 + 0]; wi = ln_w[i];
    float bi = ln_b[i];

    const float* dtp = g_dt + (size_t)b * L_;
    const float* bxp = g_bx + (size_t)b * L_ * STATE_ + i;
    float*       stp = g_states + (size_t)b * L_ * STATE_ + i;

    // prologue: h_ws = s0 + dt[ws]*(An s0) + bx[ws]
    float s0 = (ws == 0) ? state_in[b * STATE_ + i] : 0.f;
    float p0 = 0.f, p1 = 0.f, p2 = 0.f, p3 = 0.f;
    #pragma unroll
    for (int j = 0; j < 16; j += 4) {
        p0 = fmaf(an[j],     __shfl_sync(FULL, s0, j,     16), p0);
        p1 = fmaf(an[j + 1], __shfl_sync(FULL, s0, j + 1, 16), p1);
        p2 = fmaf(an[j + 2], __shfl_sync(FULL, s0, j + 2, 16), p2);
        p3 = fmaf(an[j + 3], __shfl_sync(FULL, s0, j + 3, 16), p3);
    }
    float g0 = (p0 + p1) + (p2 + p3);
    float h = fmaf(dtp[ws], g0, s0) + bxp[(size_t)ws * STATE_];

    // prefetch queue, depth 3 (g_dt/g_bx resident in L2 after K1)
    int tp1 = ws + 1; if (tp1 > L_ - 1) tp1 = L_ - 1;
    int tp2 = ws + 2; if (tp2 > L_ - 1) tp2 = L_ - 1;
    int tp3 = ws + 3; if (tp3 > L_ - 1) tp3 = L_ - 1;
    float dtA = dtp[tp1], bxA = bxp[(size_t)tp1 * STATE_];
    float dtB = dtp[tp2], bxB = bxp[(size_t)tp2 * STATE_];
    float dtC = dtp[tp3], bxC = bxp[(size_t)tp3 * STATE_];

    for (int t = ws; t < tend; ++t) {
        // broadcast h to all lanes of the group (16 independent shfls)
        float hv[16];
        #pragma unroll
        for (int j = 0; j < 16; j++) hv[j] = __shfl_sync(FULL, h, j, 16);

        // matvec g = A'h, sum u, sumsq q — all from the same hv[]
        float m0, m1, m2, m3, u0, u1, u2, u3, q0, q1, q2, q3;
        m0 = ap[0] * hv[0]; m1 = ap[1] * hv[1]; m2 = ap[2] * hv[2]; m3 = ap[3] * hv[3];
        u0 = hv[0] + hv[1]; u1 = hv[2] + hv[3];
        q0 = hv[0] * hv[0]; q1 = hv[1] * hv[1]; q2 = hv[2] * hv[2]; q3 = hv[3] * hv[3];
        #pragma unroll
        for (int j = 4; j < 16; j += 4) {
            m0 = fmaf(ap[j],     hv[j],     m0);
            m1 = fmaf(ap[j + 1], hv[j + 1], m1);
            m2 = fmaf(ap[j + 2], hv[j + 2], m2);
            m3 = fmaf(ap[j + 3], hv[j + 3], m3);
            u0 += hv[j] + hv[j + 1];
            u1 += hv[j + 2] + hv[j + 3];
            q0 = fmaf(hv[j],     hv[j],     q0);
            q1 = fmaf(hv[j + 1], hv[j + 1], q1);
            q2 = fmaf(hv[j + 2], hv[j + 2], q2);
            q3 = fmaf(hv[j + 3], hv[j + 3], q3);
        }
        float g = (m0 + m1) + (m2 + m3);
        float u = u0 + u1;
        float q = (q0 + q1) + (q2 + q3);

        float mu    = u * 0.0625f;
        float var   = fmaf(-mu, mu, q * 0.0625f);
        float alpha = rsqrtf(var + 1e-5f);
        float hm    = h - mu;

        if (t >= cs) stp[(size_t)t * STATE_] = fmaf(alpha * hm, wi, bi);

        // next pre-norm: h' = alpha*[(h-mu)*w + dt'*(g - mu*aw1)] + b + dt'*ab + bx'
        float dtn = dtA, bxn = bxA;
        dtA = dtB; bxA = bxB;
        dtB = dtC; bxB = bxC;
        int tn = t + 4; if (tn > L_ - 1) tn = L_ - 1;
        dtC = dtp[tn]; bxC = bxp[(size_t)tn * STATE_];

        float t1 = fmaf(-mu, aw1, g);
        float t2 = fmaf(dtn, t1, hm * wi);
        h = fmaf(alpha, t2, fmaf(dtn, ab, bi) + bxn);
    }
}

// =================================================================
// K3: y[b][t][d] = sum_i states[b][t][i]*W_C[d][i] + D[d]*x[b][t][d]
// Block = 64 rows (amortizes the strided W_C register staging 16x),
// thread = 4 consecutive d. Double-buffered row loads.
// =================================================================
__device__ __forceinline__ float dot16_(const float4* w,
                                        float4 s0, float4 s1, float4 s2, float4 s3) {
    float a0 = w[0].x * s0.x; a0 = fmaf(w[0].y, s0.y, a0);
    a0 = fmaf(w[0].z, s0.z, a0); a0 = fmaf(w[0].w, s0.w, a0);
    float a1 = w[1].x * s1.x; a1 = fmaf(w[1].y, s1.y, a1);
    a1 = fmaf(w[1].z, s1.z, a1); a1 = fmaf(w[1].w, s1.w, a1);
    float a2 = w[2].x * s2.x; a2 = fmaf(w[2].y, s2.y, a2);
    a2 = fmaf(w[2].z, s2.z, a2); a2 = fmaf(w[2].w, s2.w, a2);
    float a3 = w[3].x * s3.x; a3 = fmaf(w[3].y, s3.y, a3);
    a3 = fmaf(w[3].z, s3.z, a3); a3 = fmaf(w[3].w, s3.w, a3);
    return (a0 + a1) + (a2 + a3);
}

#define K3_ROWS 64

__global__ void __launch_bounds__(256) k3_out(const float* __restrict__ x,
                                              const float* __restrict__ W_C,
                                              const float* __restrict__ D,
                                              float* __restrict__ out,
                                              int write_tail) {
    int rb = blockIdx.x * K3_ROWS;
    int d  = threadIdx.x * 4;

    float4 wc[16];   // W_C[d+r][0..15] for r=0..3 (amortized over 64 rows)
    const float4* wp = reinterpret_cast<const float4*>(W_C + (size_t)d * STATE_);
    #pragma unroll
    for (int k = 0; k < 16; k++) wc[k] = wp[k];
    float4 dd = *reinterpret_cast<const float4*>(D + d);

    // double-buffered row state
    const float* st0 = g_states + (size_t)rb * STATE_;
    float4 s0 = *reinterpret_cast<const float4*>(st0);
    float4 s1 = *reinterpret_cast<const float4*>(st0 + 4);
    float4 s2 = *reinterpret_cast<const float4*>(st0 + 8);
    float4 s3 = *reinterpret_cast<const float4*>(st0 + 12);
    float4 xd = *reinterpret_cast<const float4*>(x + (size_t)rb * DIM_ + d);

    #pragma unroll 4
    for (int r = 0; r < K3_ROWS; r++) {
        int row = rb + r;
        // prefetch next row while computing this one
        float4 ns0, ns1, ns2, ns3, nxd;
        if (r + 1 < K3_ROWS) {
            const float* st = g_states + (size_t)(row + 1) * STATE_;
            ns0 = *reinterpret_cast<const float4*>(st);
            ns1 = *reinterpret_cast<const float4*>(st + 4);
            ns2 = *reinterpret_cast<const float4*>(st + 8);
            ns3 = *reinterpret_cast<const float4*>(st + 12);
            nxd = *reinterpret_cast<const float4*>(x + (size_t)(row + 1) * DIM_ + d);
        }

        float4 y;
        y.x = dot16_(wc + 0,  s0, s1, s2, s3);
        y.y = dot16_(wc + 4,  s0, s1, s2, s3);
        y.z = dot16_(wc + 8,  s0, s1, s2, s3);
        y.w = dot16_(wc + 12, s0, s1, s2, s3);
        y.x = fmaf(dd.x, xd.x, y.x);
        y.y = fmaf(dd.y, xd.y, y.y);
        y.z = fmaf(dd.z, xd.z, y.z);
        y.w = fmaf(dd.w, xd.w, y.w);
        *reinterpret_cast<float4*>(out + (size_t)row * DIM_ + d) = y;

        if (r + 1 < K3_ROWS) { s0 = ns0; s1 = ns1; s2 = ns2; s3 = ns3; xd = nxd; }
    }

    // new_state = states[:, L-1, :]
    if (write_tail && blockIdx.x == 0 && threadIdx.x < B_ * STATE_) {
        int bb = threadIdx.x >> 4, ii = threadIdx.x & 15;
        out[(size_t)B_ * L_ * DIM_ + threadIdx.x] =
            g_states[((size_t)bb * L_ + (L_ - 1)) * STATE_ + ii];
    }
}

// =================================================================
extern "C" void kernel_launch(void* const* d_in, const int* in_sizes, int n_in,
                              void* d_out, int out_size) {
    const float* x     = (const float*)d_in[0];
    const float* state = (const float*)d_in[1];
    const float* A     = (const float*)d_in[2];
    const float* W_B   = (const float*)d_in[3];
    const float* W_C   = (const float*)d_in[4];
    const float* D     = (const float*)d_in[5];
    const float* dt_w  = (const float*)d_in[6];
    const float* dt_b  = (const float*)d_in[7];
    const float* ln_w  = (const float*)d_in[8];
    const float* ln_b  = (const float*)d_in[9];
    float* out = (float*)d_out;

    k0_scale<<<1, 256>>>(A);
    k1_proj<<<(B_ * L_ / 2 * 32) / 256, 256>>>(x, W_B, dt_w, dt_b);      // 1024 blocks
    k2_scan<<<(B_ * NC_) / 2, 32>>>(A, state, ln_w, ln_b);               // 128 blocks
    int tail = (out_size >= B_ * L_ * DIM_ + B_ * STATE_) ? 1 : 0;
    k3_out<<<(B_ * L_) / K3_ROWS, 256>>>(x, W_C, D, out, tail);          // 256 blocks
}